// round 15
// baseline (speedup 1.0000x reference)
#include <cuda_runtime.h>
#include <cuda_bf16.h>

// Soft-DTW (gamma=0.1), N=M=4096, squared-Euclidean cost, out = |R[N-1,M-1]|.
//
// R15: 4x4 CELL TILE per thread. 16 blocks x 64 threads; thread t owns rows
// base+4t..base+4t+3 (base = 256b); at macro-step s it computes the 4x4 tile
// at column QUAD p = s - t (cols 4p..4p+3).
//   slots ~ 15x70 + 1024 + 64 ~ 2140 (vs 4250 at 2x2); T ~ MUFU floor
//   (16 cells x 4 MUFU x rt8 = 512) vs chain (7 cells x 64 = 448).
// Handoff payload: thread-above's BOTTOM row quad (d0..d3):
//   lanes via 4x shfl.up; warps via float4 parity wslot + per-step bar;
//   blocks via float4 boundary rows + release/acquire QUAD counter
//   (writer: 8 quads batched, 8x st.cg.v4 + ONE st.release per 8-step
//   half-group; feeder: 16-deep float4 register FIFO, group waits, early
//   acquire poll). Protocol logic byte-identical to proven R13/R14.
// Tile deps (row-major sweep, carried = col 4p-1 values {ga,la,lb,lc,ld}):
//   a_k = cell(up=u_k,    left=a_{k-1}|la, diag=u_{k-1}|ga)
//   b_k = cell(up=a_k,    left=b_{k-1}|lb, diag=a_{k-1}|la_old)
//   c_k = cell(up=b_k,    left=c_{k-1}|lc, diag=b_{k-1}|lb_old)
//   d_k = cell(up=c_k,    left=d_{k-1}|ld, diag=c_{k-1}|lc_old)
// Per-cell arithmetic identical to R13/R14 -> same rel_err 3.96e-5.
// All values scaled q = R/(gamma*ln2); softmin via ex2/lg2.approx.ftz,
// args clamped >= -150.

#define NN 4096
#define TPB 64
#define NBLK 16                  // block covers TPB*4 = 256 rows
#define NQ (NN / 4)              // 1024 column quads
#define NMSTEPS 1088             // >= NQ + TPB - 1 = 1087, multiple of 16

__device__ float4 g_bnd[(NBLK - 1) * NQ];
__device__ int    g_prog[NBLK];

__device__ __forceinline__ float ex2f_(float a) {
    float r; asm("ex2.approx.ftz.f32 %0, %1;" : "=f"(r) : "f"(a)); return r;
}
__device__ __forceinline__ float lg2f_(float a) {
    float r; asm("lg2.approx.ftz.f32 %0, %1;" : "=f"(r) : "f"(a)); return r;
}
__device__ __forceinline__ float4 ldcgf4_(const float4* p) {
    float4 v;
    asm volatile("ld.global.cg.v4.f32 {%0,%1,%2,%3}, [%4];"
                 : "=f"(v.x), "=f"(v.y), "=f"(v.z), "=f"(v.w) : "l"(p));
    return v;
}
__device__ __forceinline__ void stcgf4_(float4* p, float4 v) {
    asm volatile("st.global.cg.v4.f32 [%0], {%1,%2,%3,%4};"
                 :: "l"(p), "f"(v.x), "f"(v.y), "f"(v.z), "f"(v.w) : "memory");
}
__device__ __forceinline__ int ldacq_(const int* p) {
    int r; asm volatile("ld.acquire.gpu.global.s32 %0, [%1];" : "=r"(r) : "l"(p)); return r;
}
__device__ __forceinline__ void strel_(int* p, int v) {
    asm volatile("st.release.gpu.global.s32 [%0], %1;" :: "l"(p), "r"(v) : "memory");
}

__global__ void sdtw_reset() {
    if (threadIdx.x < NBLK) g_prog[threadIdx.x] = 0;
}

// One cell: q = d*KS + softmin(up, left, diag), scaled units.
__device__ __forceinline__ float cellq_(float dy, float up, float l, float g,
                                        float KS) {
    float m = fminf(up, fminf(l, g));
    float e = ex2f_(fmaxf(m - up, -150.0f))
            + ex2f_(fmaxf(m - l,  -150.0f))
            + ex2f_(fmaxf(m - g,  -150.0f));
    return dy * dy * KS + (m - lg2f_(e));
}

__global__ __launch_bounds__(TPB, 1)
void sdtw_main(const float* __restrict__ x, const float* __restrict__ y,
               float* __restrict__ out) {
    __shared__ float4 ysh4[NQ];           // targets as quads (16 KB)
    __shared__ float4 wslot[2][TPB / 32]; // [step parity][warp] quad handoff

    const float KS   = 14.426950408889634f;    // 1/(gamma*ln2), gamma=0.1
    const float IKS  = 0.069314718055994531f;  // gamma*ln2
    const float BIGQ = 1.0e8f;                 // "infinity" in q units

    const int tid  = threadIdx.x;
    const int b    = blockIdx.x;
    const int w    = tid >> 5;
    const int lane = tid & 31;
    const int rowA = b * (TPB * 4) + 4 * tid;
    const int wm1  = (w > 0) ? (w - 1) : 0;
    const bool rowA0 = (rowA == 0);            // only b==0, tid==0

    const float4* y4 = reinterpret_cast<const float4*>(y);
    for (int i = tid; i < NQ; i += TPB) ysh4[i] = y4[i];
    const float xi0 = x[rowA];
    const float xi1 = x[rowA + 1];
    const float xi2 = x[rowA + 2];
    const float xi3 = x[rowA + 3];

    const float4* bnd_in   = g_bnd + (b > 0 ? (b - 1) * NQ : 0);
    float4*       bnd_out  = g_bnd + (b < NBLK - 1 ? b * NQ : 0);
    const int*    prog_in  = &g_prog[b > 0 ? b - 1 : 0];
    int*          prog_out = &g_prog[b < NBLK - 1 ? b : NBLK - 1];
    const bool feeder = (tid == 0) && (b > 0);
    const bool writer = (tid == TPB - 1) && (b < NBLK - 1);

    // Feeder register FIFO: pf[k] holds boundary QUAD for macro-step sb+k.
    float4 pf[16];
    #pragma unroll
    for (int k = 0; k < 16; ++k) pf[k] = make_float4(0.f, 0.f, 0.f, 0.f);
    int avail = 0, early = 0;
    if (feeder) {
        while ((avail = ldacq_(prog_in)) < 8) {}
        #pragma unroll
        for (int k = 0; k < 8; ++k) pf[k] = ldcgf4_(bnd_in + k);
        early = avail;
    }

    // Writer register buffer: 8 boundary quads per half-group.
    float4 wbuf[8];
    #pragma unroll
    for (int k = 0; k < 8; ++k) wbuf[k] = make_float4(0.f, 0.f, 0.f, 0.f);

    __syncthreads();

    // Carried state = values at column 4p-1 after each step:
    float ga = 0.0f;                            // R[rowA-1, 4p-1] (prev uu3)
    float la = 0.0f, lb = 0.0f, lc = 0.0f, ld = 0.0f;  // rows A..D at 4p-1
    float qd0 = 0.0f, qd1 = 0.0f, qd2 = 0.0f, qd3 = 0.0f; // bottom row quad

// Guarded step (prologue/epilogue): handles p<0, p==0, p>=NQ edges.
#define STEPG(S, PFK, K)                                                      \
    {                                                                         \
        float u0 = __shfl_up_sync(0xFFFFFFFFu, qd0, 1);                       \
        float u1 = __shfl_up_sync(0xFFFFFFFFu, qd1, 1);                       \
        float u2 = __shfl_up_sync(0xFFFFFFFFu, qd2, 1);                       \
        float u3 = __shfl_up_sync(0xFFFFFFFFu, qd3, 1);                       \
        if (lane == 0) {                                                      \
            if (w > 0) {                                                      \
                float4 wv = wslot[((S) + 1) & 1][w - 1];                      \
                u0 = wv.x; u1 = wv.y; u2 = wv.z; u3 = wv.w;                   \
            } else if (b == 0) {                                              \
                u0 = BIGQ; u1 = BIGQ; u2 = BIGQ; u3 = BIGQ;                   \
            } else if ((S) < NQ) {                                            \
                u0 = (PFK).x; u1 = (PFK).y; u2 = (PFK).z; u3 = (PFK).w;       \
            }                                                                 \
        }                                                                     \
        const int p = (S) - tid;                                              \
        if (p >= 0 && p < NQ) {                                               \
            float uu0 = rowA0 ? BIGQ : u0;                                    \
            float uu1 = rowA0 ? BIGQ : u1;                                    \
            float uu2 = rowA0 ? BIGQ : u2;                                    \
            float uu3 = rowA0 ? BIGQ : u3;                                    \
            float laE = (p == 0) ? BIGQ : la;                                 \
            float gaE = (p == 0) ? (rowA0 ? 0.0f : BIGQ) : ga;                \
            float lbE = (p == 0) ? BIGQ : lb;                                 \
            float gbE = (p == 0) ? BIGQ : la;                                 \
            float lcE = (p == 0) ? BIGQ : lc;                                 \
            float gcE = (p == 0) ? BIGQ : lb;                                 \
            float ldE = (p == 0) ? BIGQ : ld;                                 \
            float gdE = (p == 0) ? BIGQ : lc;                                 \
            float4 yv = ysh4[p];                                              \
            float a0 = cellq_(xi0 - yv.x, uu0, laE, gaE, KS);                 \
            float a1 = cellq_(xi0 - yv.y, uu1, a0, uu0, KS);                  \
            float a2 = cellq_(xi0 - yv.z, uu2, a1, uu1, KS);                  \
            float a3 = cellq_(xi0 - yv.w, uu3, a2, uu2, KS);                  \
            float b0 = cellq_(xi1 - yv.x, a0, lbE, gbE, KS);                  \
            float b1 = cellq_(xi1 - yv.y, a1, b0, a0, KS);                    \
            float b2 = cellq_(xi1 - yv.z, a2, b1, a1, KS);                    \
            float b3 = cellq_(xi1 - yv.w, a3, b2, a2, KS);                    \
            float c0 = cellq_(xi2 - yv.x, b0, lcE, gcE, KS);                  \
            float c1 = cellq_(xi2 - yv.y, b1, c0, b0, KS);                    \
            float c2 = cellq_(xi2 - yv.z, b2, c1, b1, KS);                    \
            float c3 = cellq_(xi2 - yv.w, b3, c2, b2, KS);                    \
            float d0 = cellq_(xi3 - yv.x, c0, ldE, gdE, KS);                  \
            float d1 = cellq_(xi3 - yv.y, c1, d0, c0, KS);                    \
            float d2 = cellq_(xi3 - yv.z, c2, d1, c1, KS);                    \
            float d3 = cellq_(xi3 - yv.w, c3, d2, c2, KS);                    \
            ga = uu3; la = a3; lb = b3; lc = c3; ld = d3;                     \
            qd0 = d0; qd1 = d1; qd2 = d2; qd3 = d3;                           \
        }                                                                     \
        if (lane == 31) wslot[(S) & 1][w] = make_float4(qd0, qd1, qd2, qd3); \
        wbuf[K] = make_float4(qd0, qd1, qd2, qd3);                            \
        __syncthreads();                                                      \
    }

// Branchless steady step: S in [TPB, NQ) -> every lane has p in [1, NQ).
#define STEPS_(S, PFK, K)                                                     \
    {                                                                         \
        float u0 = __shfl_up_sync(0xFFFFFFFFu, qd0, 1);                       \
        float u1 = __shfl_up_sync(0xFFFFFFFFu, qd1, 1);                       \
        float u2 = __shfl_up_sync(0xFFFFFFFFu, qd2, 1);                       \
        float u3 = __shfl_up_sync(0xFFFFFFFFu, qd3, 1);                       \
        float4 wv = wslot[((S) + 1) & 1][wm1];    /* all-lane broadcast */    \
        float p0 = (b == 0) ? BIGQ : (PFK).x;                                 \
        float p1 = (b == 0) ? BIGQ : (PFK).y;                                 \
        float p2 = (b == 0) ? BIGQ : (PFK).z;                                 \
        float p3 = (b == 0) ? BIGQ : (PFK).w;                                 \
        u0 = (lane == 0) ? ((w > 0) ? wv.x : p0) : u0;                        \
        u1 = (lane == 0) ? ((w > 0) ? wv.y : p1) : u1;                        \
        u2 = (lane == 0) ? ((w > 0) ? wv.z : p2) : u2;                        \
        u3 = (lane == 0) ? ((w > 0) ? wv.w : p3) : u3;                        \
        float uu0 = rowA0 ? BIGQ : u0;                                        \
        float uu1 = rowA0 ? BIGQ : u1;                                        \
        float uu2 = rowA0 ? BIGQ : u2;                                        \
        float uu3 = rowA0 ? BIGQ : u3;                                        \
        float4 yv = ysh4[(S) - tid];                                          \
        float a0 = cellq_(xi0 - yv.x, uu0, la, ga, KS);                       \
        float a1 = cellq_(xi0 - yv.y, uu1, a0, uu0, KS);                      \
        float a2 = cellq_(xi0 - yv.z, uu2, a1, uu1, KS);                      \
        float a3 = cellq_(xi0 - yv.w, uu3, a2, uu2, KS);                      \
        float b0 = cellq_(xi1 - yv.x, a0, lb, la, KS);                        \
        float b1 = cellq_(xi1 - yv.y, a1, b0, a0, KS);                        \
        float b2 = cellq_(xi1 - yv.z, a2, b1, a1, KS);                        \
        float b3 = cellq_(xi1 - yv.w, a3, b2, a2, KS);                        \
        float c0 = cellq_(xi2 - yv.x, b0, lc, lb, KS);                        \
        float c1 = cellq_(xi2 - yv.y, b1, c0, b0, KS);                        \
        float c2 = cellq_(xi2 - yv.z, b2, c1, b1, KS);                        \
        float c3 = cellq_(xi2 - yv.w, b3, c2, b2, KS);                        \
        float d0 = cellq_(xi3 - yv.x, c0, ld, lc, KS);                        \
        float d1 = cellq_(xi3 - yv.y, c1, d0, c0, KS);                        \
        float d2 = cellq_(xi3 - yv.z, c2, d1, c1, KS);                        \
        float d3 = cellq_(xi3 - yv.w, c3, d2, c2, KS);                        \
        ga = uu3; la = a3; lb = b3; lc = c3; ld = d3;                         \
        qd0 = d0; qd1 = d1; qd2 = d2; qd3 = d3;                               \
        if (lane == 31) wslot[(S) & 1][w] = make_float4(qd0, qd1, qd2, qd3); \
        wbuf[K] = make_float4(qd0, qd1, qd2, qd3);                            \
        __syncthreads();                                                      \
    }

// Writer flush: 8 plain .cg.v4 stores + ONE release, between half-groups.
#define WFLUSH(SB)                                                            \
    if (writer) {                                                             \
        const int base = (SB) - (TPB - 1);                                    \
        _Pragma("unroll")                                                     \
        for (int k = 0; k < 8; ++k) {                                         \
            const int jj = base + k;                                          \
            if (jj >= 0 && jj < NQ) stcgf4_(bnd_out + jj, wbuf[k]);           \
        }                                                                     \
        int c = base + 8; if (c > NQ) c = NQ;                                 \
        if (c > 0) strel_(prog_out, c);                                       \
    }

// One 16-step group with the proven feeder/writer cadence.
#define GROUP16(SBX, STEPM)                                                   \
    {                                                                         \
        const int sb_ = (SBX);                                                \
        if (feeder) {                                                         \
            int lim = sb_ + 16; if (lim > NQ) lim = NQ;                       \
            if (avail < lim) {                                                \
                if (early > avail) avail = early;                             \
                while (avail < lim) avail = ldacq_(prog_in);                  \
            }                                                                 \
            _Pragma("unroll")                                                 \
            for (int k = 8; k < 16; ++k) {                                    \
                const int c = sb_ + k;                                        \
                if (c < NQ) pf[k] = ldcgf4_(bnd_in + c);                      \
            }                                                                 \
            early = ldacq_(prog_in);                                          \
        }                                                                     \
        _Pragma("unroll")                                                     \
        for (int k = 0; k < 8; ++k) STEPM(sb_ + k, pf[k], k)                  \
        WFLUSH(sb_)                                                           \
        if (feeder) {                                                         \
            int lim = sb_ + 24; if (lim > NQ) lim = NQ;                       \
            if (avail < lim) {                                                \
                if (early > avail) avail = early;                             \
                while (avail < lim) avail = ldacq_(prog_in);                  \
            }                                                                 \
            _Pragma("unroll")                                                 \
            for (int k = 0; k < 8; ++k) {                                     \
                const int c = sb_ + 16 + k;                                   \
                if (c < NQ) pf[k] = ldcgf4_(bnd_in + c);                      \
            }                                                                 \
            early = ldacq_(prog_in);                                          \
        }                                                                     \
        _Pragma("unroll")                                                     \
        for (int k = 8; k < 16; ++k) STEPM(sb_ + k, pf[k], k - 8)             \
        WFLUSH(sb_ + 8)                                                       \
    }

    // Prologue: s in [0, 64) — p<0 and p==0 edges.
    #pragma unroll 1
    for (int sb = 0; sb < TPB; sb += 16) GROUP16(sb, STEPG)

    // Steady: s in [64, 1024) — branchless.
    #pragma unroll 1
    for (int sb = TPB; sb < NQ; sb += 16) GROUP16(sb, STEPS_)

    // Epilogue: s in [1024, 1088) — p>=NQ edges; feeder idle.
    #pragma unroll 1
    for (int sb = NQ; sb < NMSTEPS; sb += 16) GROUP16(sb, STEPG)

#undef STEPG
#undef STEPS_
#undef WFLUSH
#undef GROUP16

    if (tid == TPB - 1 && b == NBLK - 1)
        out[0] = fabsf(qd3 * IKS);   // qd3 = R[4095, 4095]
}

extern "C" void kernel_launch(void* const* d_in, const int* in_sizes, int n_in,
                              void* d_out, int out_size) {
    const float* xin = (const float*)d_in[0];   // inputs  -> rows
    const float* yin = (const float*)d_in[1];   // targets -> cols
    float* outp = (float*)d_out;
    sdtw_reset<<<1, NBLK>>>();
    sdtw_main<<<NBLK, TPB>>>(xin, yin, outp);
}

// round 16
// speedup vs baseline: 1.4395x; 1.4395x over previous
#include <cuda_runtime.h>
#include <cuda_bf16.h>

// Soft-DTW (gamma=0.1), N=M=4096, squared-Euclidean cost, out = |R[N-1,M-1]|.
//
// R16 = R14 (proven 1029us, 2x2 tile, 32 blk x 64 thr) with the cell math
// rewritten in EXP DOMAIN: z = 2^(-q_scaled), so
//     z_new = w * (z_up + z_left + z_diag),   w = 2^(-d*KS)
// -- no ex2/lg2 on the dependency chain (w is data-only, computed off-chain).
// Each value is (m, n): z = m * 2^n, m in [1,2) (m=0,n=NMIN means z=0 = "inf
// cost"; BIG edges are exactly z=0, no clamps needed). Per cell: align the 3
// terms to max-n with bit-built scales (underflow -> 0 is correct), FFMA-sum,
// multiply by mw, renormalize via exponent bit-extraction. Int ops ride the
// ALU pipe alongside FP.
//   Protocol/skeleton byte-identical to R14: shfl x4 (m,n pairs); float4
//   parity wslot + per-step bar; float4 boundary rows (n's bitcast) +
//   release/acquire pair counter; writer 8-step batched flush + ONE release;
//   feeder 16-deep float4 register FIFO; guarded/branchless phase split.
// Accuracy: aligned fp32 sum drops sub-2^-24 terms exactly like reference
// fp32 logsumexp; expected rel_err ~1e-5 (no longer bit-identical to R14).

#define NN 4096
#define TPB 64
#define NBLK 32                  // block covers TPB*2 = 128 rows
#define NPAIR (NN / 2)           // 2048 column pairs
#define NMSTEPS 2112             // >= NPAIR + TPB - 1 = 2111, multiple of 16
#define NMIN (-(1 << 29))        // exponent of an exact-zero z

__device__ float4 g_bnd[(NBLK - 1) * NPAIR];
__device__ int    g_prog[NBLK];

__device__ __forceinline__ float ex2f_(float a) {
    float r; asm("ex2.approx.ftz.f32 %0, %1;" : "=f"(r) : "f"(a)); return r;
}
__device__ __forceinline__ float lg2f_(float a) {
    float r; asm("lg2.approx.ftz.f32 %0, %1;" : "=f"(r) : "f"(a)); return r;
}
__device__ __forceinline__ float4 ldcgf4_(const float4* p) {
    float4 v;
    asm volatile("ld.global.cg.v4.f32 {%0,%1,%2,%3}, [%4];"
                 : "=f"(v.x), "=f"(v.y), "=f"(v.z), "=f"(v.w) : "l"(p));
    return v;
}
__device__ __forceinline__ void stcgf4_(float4* p, float4 v) {
    asm volatile("st.global.cg.v4.f32 [%0], {%1,%2,%3,%4};"
                 :: "l"(p), "f"(v.x), "f"(v.y), "f"(v.z), "f"(v.w) : "memory");
}
__device__ __forceinline__ int ldacq_(const int* p) {
    int r; asm volatile("ld.acquire.gpu.global.s32 %0, [%1];" : "=r"(r) : "l"(p)); return r;
}
__device__ __forceinline__ void strel_(int* p, int v) {
    asm volatile("st.release.gpu.global.s32 [%0], %1;" :: "l"(p), "r"(v) : "memory");
}

__global__ void sdtw_reset() {
    if (threadIdx.x < NBLK) g_prog[threadIdx.x] = 0;
}

// 2^d for d <= 0, clamped to 0 below 2^-126 (dropped terms are negligible,
// matching fp32 logsumexp truncation).
__device__ __forceinline__ float scalef_(int d) {
    int t = 127 + d;
    t = (t > 0) ? t : 0;
    return __int_as_float(t << 23);
}

// One exp-domain cell: z_out = w * (z_u + z_l + z_g); all z's as (m, n).
__device__ __forceinline__ void cellz_(
    float um, int un, float lm, int ln_, float gm, int gn,
    float mw, int nw, float& om, int& on)
{
    int nmax = max(un, max(ln_, gn));
    float su = scalef_(un  - nmax);
    float sl = scalef_(ln_ - nmax);
    float sg = scalef_(gn  - nmax);
    float s  = um * su + lm * sl + gm * sg;   // FMUL + FFMA + FFMA
    float mo = s * mw;                        // mo in (0.5, 6) when valid
    int bits = __float_as_int(mo);
    om = __int_as_float((bits & 0x007FFFFF) | 0x3F800000);  // renorm [1,2)
    on = nmax - nw + ((bits >> 23) - 127);
}

// Per-cell weight w = 2^(-dk) as (mw in (0.5,1], nw int): data-only.
#define MKW(D, MW, NW)                                                        \
    float MW; int NW;                                                         \
    { float dk_ = (D) * (D) * KS; float f_ = floorf(dk_);                     \
      MW = ex2f_(f_ - dk_); NW = (int)f_; }

__global__ __launch_bounds__(TPB, 1)
void sdtw_main(const float* __restrict__ x, const float* __restrict__ y,
               float* __restrict__ out) {
    __shared__ float2 ysh2[NPAIR];        // targets as pairs (16 KB)
    __shared__ float4 wslot[2][TPB / 32]; // [parity][warp] (m0,n0,m1,n1)

    const float KS  = 14.426950408889634f;    // 1/(gamma*ln2), gamma=0.1
    const float IKS = 0.069314718055994531f;  // gamma*ln2

    const int tid  = threadIdx.x;
    const int b    = blockIdx.x;
    const int w    = tid >> 5;
    const int lane = tid & 31;
    const int rowA = b * (TPB * 2) + 2 * tid;
    const int wm1  = (w > 0) ? (w - 1) : 0;
    const bool rowA0 = (rowA == 0);            // only b==0, tid==0

    const float2* y2 = reinterpret_cast<const float2*>(y);
    for (int i = tid; i < NPAIR; i += TPB) ysh2[i] = y2[i];
    const float xi0 = x[rowA];
    const float xi1 = x[rowA + 1];

    const float4* bnd_in   = g_bnd + (b > 0 ? (b - 1) * NPAIR : 0);
    float4*       bnd_out  = g_bnd + (b < NBLK - 1 ? b * NPAIR : 0);
    const int*    prog_in  = &g_prog[b > 0 ? b - 1 : 0];
    int*          prog_out = &g_prog[b < NBLK - 1 ? b : NBLK - 1];
    const bool feeder = (tid == 0) && (b > 0);
    const bool writer = (tid == TPB - 1) && (b < NBLK - 1);

    // Feeder register FIFO: pf[k] = boundary (m0,n0,m1,n1) for step sb+k.
    float4 pf[16];
    #pragma unroll
    for (int k = 0; k < 16; ++k) pf[k] = make_float4(0.f, 0.f, 0.f, 0.f);
    int avail = 0, early = 0;
    if (feeder) {
        while ((avail = ldacq_(prog_in)) < 8) {}
        #pragma unroll
        for (int k = 0; k < 8; ++k) pf[k] = ldcgf4_(bnd_in + k);
        early = avail;
    }

    float4 wbuf[8];
    #pragma unroll
    for (int k = 0; k < 8; ++k) wbuf[k] = make_float4(0.f, 0.f, 0.f, 0.f);

    __syncthreads();

    // Carried state (column 2p-1 values after each step), all (m, n):
    float qa1m = 0.f; int qa1n = NMIN;   // z(R[rowA,   2p-1])
    float dgam = 0.f; int dgan = NMIN;   // z(R[rowA-1, 2p-1]) (prev uu1)
    float qb0m = 0.f; int qb0n = NMIN;   // z(R[rowB, 2p])   -> handoff
    float qb1m = 0.f; int qb1n = NMIN;   // z(R[rowB, 2p+1]) -> handoff

// Guarded step (prologue/epilogue): handles p<0, p==0, p>=NPAIR edges.
#define STEPG(S, PFK, K)                                                      \
    {                                                                         \
        float u0m = __shfl_up_sync(0xFFFFFFFFu, qb0m, 1);                     \
        int   u0n = __shfl_up_sync(0xFFFFFFFFu, qb0n, 1);                     \
        float u1m = __shfl_up_sync(0xFFFFFFFFu, qb1m, 1);                     \
        int   u1n = __shfl_up_sync(0xFFFFFFFFu, qb1n, 1);                     \
        if (lane == 0) {                                                      \
            if (w > 0) {                                                      \
                float4 wv = wslot[((S) + 1) & 1][w - 1];                      \
                u0m = wv.x; u0n = __float_as_int(wv.y);                       \
                u1m = wv.z; u1n = __float_as_int(wv.w);                       \
            } else if (b == 0) {                                              \
                u0m = 0.f; u0n = NMIN; u1m = 0.f; u1n = NMIN;                 \
            } else if ((S) < NPAIR) {                                         \
                u0m = (PFK).x; u0n = __float_as_int((PFK).y);                 \
                u1m = (PFK).z; u1n = __float_as_int((PFK).w);                 \
            }                                                                 \
        }                                                                     \
        const int p = (S) - tid;                                              \
        if (p >= 0 && p < NPAIR) {                                            \
            float uu0m = rowA0 ? 0.f : u0m; int uu0n = rowA0 ? NMIN : u0n;    \
            float uu1m = rowA0 ? 0.f : u1m; int uu1n = rowA0 ? NMIN : u1n;    \
            float lam = (p == 0) ? 0.f : qa1m;                                \
            int   lan = (p == 0) ? NMIN : qa1n;                               \
            float gam = (p == 0) ? (rowA0 ? 1.f : 0.f) : dgam;                \
            int   gan = (p == 0) ? (rowA0 ? 0 : NMIN) : dgan;                 \
            float lbm = (p == 0) ? 0.f : qb1m;                                \
            int   lbn = (p == 0) ? NMIN : qb1n;                               \
            float gbm = (p == 0) ? 0.f : qa1m;                                \
            int   gbn = (p == 0) ? NMIN : qa1n;                               \
            float2 yv = ysh2[p];                                              \
            MKW(xi0 - yv.x, mw00, nw00)                                       \
            MKW(xi0 - yv.y, mw01, nw01)                                       \
            MKW(xi1 - yv.x, mw10, nw10)                                       \
            MKW(xi1 - yv.y, mw11, nw11)                                       \
            float a0m; int a0n;                                               \
            cellz_(uu0m, uu0n, lam, lan, gam, gan, mw00, nw00, a0m, a0n);     \
            float a1m; int a1n;                                               \
            cellz_(uu1m, uu1n, a0m, a0n, uu0m, uu0n, mw01, nw01, a1m, a1n);   \
            float b0m_; int b0n_;                                             \
            cellz_(a0m, a0n, lbm, lbn, gbm, gbn, mw10, nw10, b0m_, b0n_);     \
            float b1m_; int b1n_;                                             \
            cellz_(a1m, a1n, b0m_, b0n_, a0m, a0n, mw11, nw11, b1m_, b1n_);   \
            dgam = uu1m; dgan = uu1n; qa1m = a1m; qa1n = a1n;                 \
            qb0m = b0m_; qb0n = b0n_; qb1m = b1m_; qb1n = b1n_;               \
        }                                                                     \
        if (lane == 31) wslot[(S) & 1][w] =                                   \
            make_float4(qb0m, __int_as_float(qb0n),                           \
                        qb1m, __int_as_float(qb1n));                          \
        wbuf[K] = make_float4(qb0m, __int_as_float(qb0n),                     \
                              qb1m, __int_as_float(qb1n));                    \
        __syncthreads();                                                      \
    }

// Branchless steady step: S in [TPB, NPAIR) -> every lane has p in [1,NPAIR).
#define STEPS_(S, PFK, K)                                                     \
    {                                                                         \
        float u0m = __shfl_up_sync(0xFFFFFFFFu, qb0m, 1);                     \
        int   u0n = __shfl_up_sync(0xFFFFFFFFu, qb0n, 1);                     \
        float u1m = __shfl_up_sync(0xFFFFFFFFu, qb1m, 1);                     \
        int   u1n = __shfl_up_sync(0xFFFFFFFFu, qb1n, 1);                     \
        float4 wv = wslot[((S) + 1) & 1][wm1];    /* all-lane broadcast */    \
        float pm0 = (b == 0) ? 0.f : (PFK).x;                                 \
        int   pn0 = (b == 0) ? NMIN : __float_as_int((PFK).y);                \
        float pm1 = (b == 0) ? 0.f : (PFK).z;                                 \
        int   pn1 = (b == 0) ? NMIN : __float_as_int((PFK).w);                \
        u0m = (lane == 0) ? ((w > 0) ? wv.x : pm0) : u0m;                     \
        u0n = (lane == 0) ? ((w > 0) ? __float_as_int(wv.y) : pn0) : u0n;     \
        u1m = (lane == 0) ? ((w > 0) ? wv.z : pm1) : u1m;                     \
        u1n = (lane == 0) ? ((w > 0) ? __float_as_int(wv.w) : pn1) : u1n;     \
        float uu0m = rowA0 ? 0.f : u0m; int uu0n = rowA0 ? NMIN : u0n;        \
        float uu1m = rowA0 ? 0.f : u1m; int uu1n = rowA0 ? NMIN : u1n;        \
        float2 yv = ysh2[(S) - tid];                                          \
        MKW(xi0 - yv.x, mw00, nw00)                                           \
        MKW(xi0 - yv.y, mw01, nw01)                                           \
        MKW(xi1 - yv.x, mw10, nw10)                                           \
        MKW(xi1 - yv.y, mw11, nw11)                                           \
        float a0m; int a0n;                                                   \
        cellz_(uu0m, uu0n, qa1m, qa1n, dgam, dgan, mw00, nw00, a0m, a0n);     \
        float a1m; int a1n;                                                   \
        cellz_(uu1m, uu1n, a0m, a0n, uu0m, uu0n, mw01, nw01, a1m, a1n);       \
        float b0m_; int b0n_;                                                 \
        cellz_(a0m, a0n, qb1m, qb1n, qa1m, qa1n, mw10, nw10, b0m_, b0n_);     \
        float b1m_; int b1n_;                                                 \
        cellz_(a1m, a1n, b0m_, b0n_, a0m, a0n, mw11, nw11, b1m_, b1n_);       \
        dgam = uu1m; dgan = uu1n; qa1m = a1m; qa1n = a1n;                     \
        qb0m = b0m_; qb0n = b0n_; qb1m = b1m_; qb1n = b1n_;                   \
        if (lane == 31) wslot[(S) & 1][w] =                                   \
            make_float4(qb0m, __int_as_float(qb0n),                           \
                        qb1m, __int_as_float(qb1n));                          \
        wbuf[K] = make_float4(qb0m, __int_as_float(qb0n),                     \
                              qb1m, __int_as_float(qb1n));                    \
        __syncthreads();                                                      \
    }

// Writer flush: 8 plain .cg.v4 stores + ONE release, between half-groups.
#define WFLUSH(SB)                                                            \
    if (writer) {                                                             \
        const int base = (SB) - (TPB - 1);                                    \
        _Pragma("unroll")                                                     \
        for (int k = 0; k < 8; ++k) {                                         \
            const int jj = base + k;                                          \
            if (jj >= 0 && jj < NPAIR) stcgf4_(bnd_out + jj, wbuf[k]);        \
        }                                                                     \
        int c = base + 8; if (c > NPAIR) c = NPAIR;                           \
        if (c > 0) strel_(prog_out, c);                                       \
    }

// One 16-step group with the proven feeder/writer cadence.
#define GROUP16(SBX, STEPM)                                                   \
    {                                                                         \
        const int sb_ = (SBX);                                                \
        if (feeder) {                                                         \
            int lim = sb_ + 16; if (lim > NPAIR) lim = NPAIR;                 \
            if (avail < lim) {                                                \
                if (early > avail) avail = early;                             \
                while (avail < lim) avail = ldacq_(prog_in);                  \
            }                                                                 \
            _Pragma("unroll")                                                 \
            for (int k = 8; k < 16; ++k) {                                    \
                const int c = sb_ + k;                                        \
                if (c < NPAIR) pf[k] = ldcgf4_(bnd_in + c);                   \
            }                                                                 \
            early = ldacq_(prog_in);                                          \
        }                                                                     \
        _Pragma("unroll")                                                     \
        for (int k = 0; k < 8; ++k) STEPM(sb_ + k, pf[k], k)                  \
        WFLUSH(sb_)                                                           \
        if (feeder) {                                                         \
            int lim = sb_ + 24; if (lim > NPAIR) lim = NPAIR;                 \
            if (avail < lim) {                                                \
                if (early > avail) avail = early;                             \
                while (avail < lim) avail = ldacq_(prog_in);                  \
            }                                                                 \
            _Pragma("unroll")                                                 \
            for (int k = 0; k < 8; ++k) {                                     \
                const int c = sb_ + 16 + k;                                   \
                if (c < NPAIR) pf[k] = ldcgf4_(bnd_in + c);                   \
            }                                                                 \
            early = ldacq_(prog_in);                                          \
        }                                                                     \
        _Pragma("unroll")                                                     \
        for (int k = 8; k < 16; ++k) STEPM(sb_ + k, pf[k], k - 8)             \
        WFLUSH(sb_ + 8)                                                       \
    }

    // Prologue: s in [0, 64) — p<0 and p==0 edges.
    #pragma unroll 1
    for (int sb = 0; sb < TPB; sb += 16) GROUP16(sb, STEPG)

    // Steady: s in [64, 2048) — branchless.
    #pragma unroll 1
    for (int sb = TPB; sb < NPAIR; sb += 16) GROUP16(sb, STEPS_)

    // Epilogue: s in [2048, 2112) — p>=NPAIR edges; feeder idle.
    #pragma unroll 1
    for (int sb = NPAIR; sb < NMSTEPS; sb += 16) GROUP16(sb, STEPG)

#undef STEPG
#undef STEPS_
#undef WFLUSH
#undef GROUP16

    if (tid == TPB - 1 && b == NBLK - 1) {
        // q_scaled = -lg2(z) = -(n + lg2(m)); out = |q_scaled * gamma*ln2|
        float qsc = -((float)qb1n + lg2f_(qb1m));
        out[0] = fabsf(qsc * IKS);
    }
}

extern "C" void kernel_launch(void* const* d_in, const int* in_sizes, int n_in,
                              void* d_out, int out_size) {
    const float* xin = (const float*)d_in[0];   // inputs  -> rows
    const float* yin = (const float*)d_in[1];   // targets -> cols
    float* outp = (float*)d_out;
    sdtw_reset<<<1, NBLK>>>();
    sdtw_main<<<NBLK, TPB>>>(xin, yin, outp);
}